// round 1
// baseline (speedup 1.0000x reference)
#include <cuda_runtime.h>

// ---------------- problem constants ----------------
#define Bn   16
#define Nn   2048
#define DIN  512
#define DK   10
#define NH   2
#define DH   5
#define HID  20
#define DOUT 512
#define BH   (Bn * NH)          // 32
#define ROWS (Bn * Nn)          // 32768

// ---------------- device scratch (no allocation allowed) ----------------
// Q/K/V padded to 8 floats per token for aligned float4 access.
// Q is pre-scaled by 1/sqrt(DH).
__device__ float g_Q[BH][Nn][8];
__device__ float g_K[BH][Nn][8];
__device__ float g_V[BH][Nn][8];
__device__ float g_C[ROWS][DK];   // attention output, concat layout [row][h*5+d]

// =====================================================================
// Kernel 1: fused QKV projection.
// Block: 256 threads = 128 rows x 2 j-halves. Each thread accumulates 15 of
// the 30 outputs (j = 2*i + jh) for its row over the full K=512 reduction,
// staging x tiles in smem (coalesced) and W (30 cols of Wq|Wk|Wv) in smem.
// =====================================================================
#define PR   128     // rows per block
#define PKC  64      // k-chunk
#define XPAD 68      // row stride in smem (multiple of 4 for float4)

__global__ __launch_bounds__(256) void proj_kernel(
    const float* __restrict__ x,
    const float* __restrict__ Wq, const float* __restrict__ bq,
    const float* __restrict__ Wk, const float* __restrict__ bk,
    const float* __restrict__ Wv, const float* __restrict__ bv)
{
    __shared__ __align__(16) float xs[PR * XPAD];
    __shared__ __align__(16) float ws[PKC * 32];   // ws[k*32 + j], j in [0,30)

    const int tid  = threadIdx.x;
    const int row  = tid & 127;      // 0..127
    const int jh   = tid >> 7;       // 0 or 1
    const int row0 = blockIdx.x * PR;

    float acc[15];
#pragma unroll
    for (int i = 0; i < 15; i++) acc[i] = 0.f;

    for (int kc = 0; kc < DIN; kc += PKC) {
        __syncthreads();   // protect smem reads of previous chunk
        // load x tile: 128 rows x 64 cols, coalesced float4
        for (int e = tid; e < PR * PKC / 4; e += 256) {
            int r  = e >> 4;        // 16 float4 per row
            int c4 = e & 15;
            float4 v = *reinterpret_cast<const float4*>(
                x + (size_t)(row0 + r) * DIN + kc + c4 * 4);
            *reinterpret_cast<float4*>(xs + r * XPAD + c4 * 4) = v;
        }
        // load W tile: 64 k x 30 j  (j<10 -> Wq, <20 -> Wk, else Wv)
        for (int e = tid; e < PKC * 30; e += 256) {
            int k = e / 30, j = e % 30;
            float w;
            if (j < 10)      w = Wq[(kc + k) * DK + j];
            else if (j < 20) w = Wk[(kc + k) * DK + (j - 10)];
            else             w = Wv[(kc + k) * DK + (j - 20)];
            ws[k * 32 + j] = w;
        }
        __syncthreads();

        // main FMA loop: per k, 1 broadcast-ish x value, 15 FMAs
        for (int k = 0; k < PKC; k += 4) {
            float4 xv = *reinterpret_cast<const float4*>(xs + row * XPAD + k);
            const float* wr = ws + k * 32 + jh;
#pragma unroll
            for (int kk = 0; kk < 4; kk++) {
                float xk = (kk == 0) ? xv.x : (kk == 1) ? xv.y : (kk == 2) ? xv.z : xv.w;
                const float* w = wr + kk * 32;
#pragma unroll
                for (int i = 0; i < 15; i++)
                    acc[i] = fmaf(xk, w[2 * i], acc[i]);
            }
        }
    }

    // epilogue: bias + scatter into head-major Q/K/V (Q pre-scaled by 1/sqrt(5))
    const int grow = row0 + row;
    const int b = grow / Nn, n = grow % Nn;
    const float rs = rsqrtf(5.0f);
#pragma unroll
    for (int i = 0; i < 15; i++) {
        int j     = 2 * i + jh;
        int which = j / 10;          // 0=q 1=k 2=v
        int jj    = j % 10;
        int h     = jj / DH, d = jj % DH;
        int bh    = b * NH + h;
        float bias = (which == 0) ? bq[jj] : (which == 1) ? bk[jj] : bv[jj];
        float val  = acc[i] + bias;
        if (which == 0)      g_Q[bh][n][d] = val * rs;
        else if (which == 1) g_K[bh][n][d] = val;
        else                 g_V[bh][n][d] = val;
    }
}

// =====================================================================
// Kernel 2: streaming causal attention with sin-activated scores.
// sin() in [-1,1] => no running-max needed: weight = exp(sin(q.k/sqrt(5))).
// Block = 128 threads = 128 queries of one (b,h); loop causal key tiles of
// 128 in smem (broadcast LDS). Grid (16 q-tiles, 32 bh).
// =====================================================================
#define TK 128

template <bool DIAG>
__device__ __forceinline__ void attn_tile(
    const float4* __restrict__ sK4, const float4* __restrict__ sV4,
    const float2* __restrict__ sKV,
    float4 q03, float q4, int lim,
    float& a0, float& a1, float& a2, float& a3, float& a4, float& den)
{
#pragma unroll 8
    for (int jj = 0; jj < TK; jj++) {
        float4 k03 = sK4[jj];
        float2 kv  = sKV[jj];          // (k4, v4)
        float4 v03 = sV4[jj];
        float s = fmaf(q03.x, k03.x,
                  fmaf(q03.y, k03.y,
                  fmaf(q03.z, k03.z,
                  fmaf(q03.w, k03.w, q4 * kv.x))));
        float e = __expf(__sinf(s));
        if (DIAG) e = (jj <= lim) ? e : 0.f;
        den += e;
        a0 = fmaf(e, v03.x, a0);
        a1 = fmaf(e, v03.y, a1);
        a2 = fmaf(e, v03.z, a2);
        a3 = fmaf(e, v03.w, a3);
        a4 = fmaf(e, kv.y, a4);
    }
}

__global__ __launch_bounds__(128) void attn_kernel()
{
    __shared__ __align__(16) float4 sK4[TK];
    __shared__ __align__(16) float4 sV4[TK];
    __shared__ __align__(16) float2 sKV[TK];

    const int tid = threadIdx.x;
    const int qt  = blockIdx.x;
    const int bh  = blockIdx.y;
    const int qi  = qt * TK + tid;

    const float* qp = g_Q[bh][qi];
    float4 q03 = *reinterpret_cast<const float4*>(qp);
    float  q4  = qp[4];

    float a0 = 0.f, a1 = 0.f, a2 = 0.f, a3 = 0.f, a4 = 0.f, den = 0.f;

    for (int kt = 0; kt <= qt; kt++) {
        const int j = kt * TK + tid;
        const float* kp = g_K[bh][j];
        const float* vp = g_V[bh][j];
        float4 kk = *reinterpret_cast<const float4*>(kp);
        float4 vv = *reinterpret_cast<const float4*>(vp);
        float  k4 = kp[4], v4 = vp[4];
        __syncthreads();
        sK4[tid] = kk;
        sV4[tid] = vv;
        sKV[tid] = make_float2(k4, v4);
        __syncthreads();

        if (kt < qt)
            attn_tile<false>(sK4, sV4, sKV, q03, q4, 0,   a0, a1, a2, a3, a4, den);
        else
            attn_tile<true >(sK4, sV4, sKV, q03, q4, tid, a0, a1, a2, a3, a4, den);
    }

    const float inv = __fdividef(1.f, den);
    const int b = bh >> 1, h = bh & 1;
    float* op = &g_C[(size_t)b * Nn + qi][h * DH];
    op[0] = a0 * inv;
    op[1] = a1 * inv;
    op[2] = a2 * inv;
    op[3] = a3 * inv;
    op[4] = a4 * inv;
}

// =====================================================================
// Kernel 3: MLP head. Block = 256 threads handles 32 rows.
// Wm2 (20x512, 40KB) staged in smem once per block; h1 (20) per row in smem
// then registers. Each thread owns (row = tid/8, col-group = tid%8) and emits
// float4 outputs; all Wm2 LDS are conflict-free multicast.
// =====================================================================
#define MR 32

__global__ __launch_bounds__(256) void mlp_kernel(
    const float* __restrict__ Wm1, const float* __restrict__ bm1,
    const float* __restrict__ Wm2, const float* __restrict__ bm2,
    float* __restrict__ out)
{
    __shared__ __align__(16) float w2s[HID * DOUT];  // 40 KB
    __shared__ __align__(16) float h1s[MR * HID];

    const int tid  = threadIdx.x;
    const int row0 = blockIdx.x * MR;

    // stage Wm2
    for (int e = tid; e < HID * DOUT / 4; e += 256)
        reinterpret_cast<float4*>(w2s)[e] = reinterpret_cast<const float4*>(Wm2)[e];

    // h1 = leaky_relu(concat @ Wm1 + bm1): 640 elements
    for (int e = tid; e < MR * HID; e += 256) {
        int r = e / HID, j = e % HID;
        const float* crow = g_C[row0 + r];
        float s = bm1[j];
#pragma unroll
        for (int k = 0; k < DK; k++)
            s = fmaf(crow[k], Wm1[k * HID + j], s);
        h1s[e] = (s > 0.f) ? s : 0.01f * s;
    }
    __syncthreads();

    const int r  = tid >> 3;   // 0..31
    const int cg = tid & 7;    // 0..7
    float h[HID];
#pragma unroll
    for (int k = 0; k < HID; k++) h[k] = h1s[r * HID + k];

    float* orow = out + (size_t)(row0 + r) * DOUT;
#pragma unroll 2
    for (int c4 = cg; c4 < DOUT / 4; c4 += 8) {
        float4 a = reinterpret_cast<const float4*>(bm2)[c4];
#pragma unroll
        for (int k = 0; k < HID; k++) {
            float4 w = *reinterpret_cast<const float4*>(w2s + k * DOUT + c4 * 4);
            float hk = h[k];
            a.x = fmaf(hk, w.x, a.x);
            a.y = fmaf(hk, w.y, a.y);
            a.z = fmaf(hk, w.z, a.z);
            a.w = fmaf(hk, w.w, a.w);
        }
        reinterpret_cast<float4*>(orow)[c4] = a;
    }
}

// =====================================================================
extern "C" void kernel_launch(void* const* d_in, const int* in_sizes, int n_in,
                              void* d_out, int out_size)
{
    const float* x   = (const float*)d_in[0];
    const float* Wq  = (const float*)d_in[1];
    const float* bq  = (const float*)d_in[2];
    const float* Wk  = (const float*)d_in[3];
    const float* bk  = (const float*)d_in[4];
    const float* Wv  = (const float*)d_in[5];
    const float* bv  = (const float*)d_in[6];
    const float* Wm1 = (const float*)d_in[7];
    const float* bm1 = (const float*)d_in[8];
    const float* Wm2 = (const float*)d_in[9];
    const float* bm2 = (const float*)d_in[10];

    proj_kernel<<<ROWS / PR, 256>>>(x, Wq, bq, Wk, bk, Wv, bv);
    attn_kernel<<<dim3(Nn / TK, BH), 128>>>();
    mlp_kernel<<<ROWS / MR, 256>>>(Wm1, bm1, Wm2, bm2, (float*)d_out);
}